// round 16
// baseline (speedup 1.0000x reference)
#include <cuda_runtime.h>
#include <math.h>

// Problem dims (fixed by the reference)
#define NB 2048   // batch
#define NI 256    // inner / contraction dim j
#define NO 256    // output dim i

#define J_CH 16                    // j per warp-private smem stage
#define NCHUNK (NI / J_CH)         // 16
// per-warp per-phase buffer (floats): cx[128] sx[128] nc[256] so[256]
#define WB_SX 128
#define WB_NC 256
#define WB_SO 512
#define WBUF_FLOATS 768            // 3 KB
#define WBUF_BYTES  3072
#define WSTRIDE_FLOATS 1536        // 2 phases per warp
#define SMEM_BYTES (4 * 2 * WBUF_BYTES)   // 24 KB per CTA

typedef unsigned long long ull;

// Global trig tables, pair-interleaved j-major:
//   float index = (j2*R + r)*2 + (j&1),  R = NB (x-side) or NO (o-side)
__device__ __align__(16) float g_cx2[NI * NB];  // cos(phi0 + x)
__device__ __align__(16) float g_sx2[NI * NB];  // sin(phi0 + x)
__device__ __align__(16) float g_nc2[NI * NO];  // -2*rho*cos(off)
__device__ __align__(16) float g_so2[NI * NO];  //  2*rho*sin(off)

// ---------------- prep: both tables, coalesced float2 writes ----------------
__global__ void prep_all(const float* __restrict__ x, const float* __restrict__ off,
                         float phi0, float two_rho) {
    __shared__ float tile[32][33];
    const int blk = blockIdx.x;
    const float* src;
    float *dc, *ds;
    int R, r0, j0;
    float addp, mc, ms;
    if (blk < 512) {               // x-table: 64 b-tiles x 8 j-tiles
        r0 = (blk >> 3) * 32; j0 = (blk & 7) * 32;
        src = x;  dc = g_cx2; ds = g_sx2; R = NB;
        addp = phi0; mc = 1.0f; ms = 1.0f;
    } else {                       // off-table: 8 i-tiles x 8 j-tiles
        int q = blk - 512;
        r0 = (q >> 3) * 32; j0 = (q & 7) * 32;
        src = off; dc = g_nc2; ds = g_so2; R = NO;
        addp = 0.0f; mc = -two_rho; ms = two_rho;
    }
    const int lane = threadIdx.x & 31;
    const int w8   = threadIdx.x >> 5;   // 0..7
    #pragma unroll
    for (int rr = 0; rr < 4; ++rr)
        tile[w8 + rr * 8][lane] = src[(r0 + w8 + rr * 8) * NI + j0 + lane];
    __syncthreads();
    #pragma unroll
    for (int k = 0; k < 2; ++k) {
        const int jp = w8 + k * 8;       // local j-pair 0..15
        const int ri = lane;
        float s0, c0, s1, c1;
        __sincosf(addp + tile[ri][2 * jp    ], &s0, &c0);
        __sincosf(addp + tile[ri][2 * jp + 1], &s1, &c1);
        const int cell = ((j0 >> 1) + jp) * R + (r0 + ri);
        *(float2*)(dc + cell * 2) = make_float2(mc * c0, mc * c1);
        *(float2*)(ds + cell * 2) = make_float2(ms * s0, ms * s1);
    }
}

// ---------------- packed f32x2 + misc helpers ----------------
__device__ __forceinline__ ull ffma2(ull a, ull b, ull c) {
    ull d;
    asm("fma.rn.f32x2 %0, %1, %2, %3;" : "=l"(d) : "l"(a), "l"(b), "l"(c));
    return d;
}
__device__ __forceinline__ ull fadd2(ull a, ull b) {
    ull d;
    asm("add.rn.f32x2 %0, %1, %2;" : "=l"(d) : "l"(a), "l"(b));
    return d;
}
__device__ __forceinline__ ull fmul2(ull a, ull b) {
    ull d;
    asm("mul.rn.f32x2 %0, %1, %2;" : "=l"(d) : "l"(a), "l"(b));
    return d;
}
__device__ __forceinline__ float2 u2f(ull v) {
    float2 r;
    asm("mov.b64 {%0, %1}, %2;" : "=f"(r.x), "=f"(r.y) : "l"(v));
    return r;
}
__device__ __forceinline__ float frcp(float x) {
    float r;
    asm("rcp.approx.f32 %0, %1;" : "=f"(r) : "f"(x));
    return r;
}
__device__ __forceinline__ void cp16(unsigned dst, const void* src) {
    asm volatile("cp.async.ca.shared.global [%0], [%1], 16;\n" :: "r"(dst), "l"(src));
}

// 4 j-terms fused: sum 1/d = (S.x*P.y + S.y*P.x) * rcp(P.x*P.y), S=D+E, P=D*E.
#define QCELL(acc, cA, sA, cB, sB, nA, oA, nB, oB)                     \
    do {                                                               \
        ull D_ = ffma2((cA), (nA), ffma2((sA), (oA), Q2));             \
        ull E_ = ffma2((cB), (nB), ffma2((sB), (oB), Q2));             \
        float2 S_ = u2f(fadd2(D_, E_));                                \
        float2 P_ = u2f(fmul2(D_, E_));                                \
        (acc) = fmaf(fmaf(S_.x, P_.y, S_.y * P_.x),                    \
                     frcp(P_.x * P_.y), (acc));                        \
    } while (0)

// CTA: 128 threads = 4 warps, CTA tile 16(b) x 32(i).
// Each WARP owns a private 8(b) x 16(i) sub-tile and private double-buffered
// smem (2 x 3 KB): cp.async pipeline with wait_group + __syncwarp only —
// NO __syncthreads, no cross-warp convoying.
// grid (128, 8) = 1024 CTAs -> ~7 CTAs/SM, wave imbalance ~1.01.
__global__ __launch_bounds__(128, 7) void photonic_main(float* __restrict__ out,
                                                        ull Q2, float negK) {
    extern __shared__ __align__(16) float sbuf[];   // 4 warps * 6 KB

    const int t   = threadIdx.x;
    const int l   = t & 31;
    const int wid = t >> 5;                  // 0..3
    const int tx  = l & 3;                   // 4 groups along b (2 b each)
    const int ty  = l >> 2;                  // 8 groups along i (2 i each)
    const int wb0 = blockIdx.x * 16 + (wid & 1) * 8;   // warp's 8-b start
    const int wi0 = blockIdx.y * 32 + (wid >> 1) * 16; // warp's 16-i start

    float* wbuf = sbuf + wid * WSTRIDE_FLOATS;
    const unsigned sb = (unsigned)__cvta_generic_to_shared(wbuf);

    // fill sources: per chunk, warp moves 192 granules of 16B -> 6 per lane.
    // x-tables: 32 granules each (8 j-pair rows x 64B); lane l -> row l>>2, seg l&3.
    // o-tables: 64 granules each (8 rows x 128B); lane l -> granules l and l+32.
    const float* pxc = g_cx2 + ((l >> 2) * NB + wb0) * 2 + (l & 3) * 4;
    const float* pxs = g_sx2 + ((l >> 2) * NB + wb0) * 2 + (l & 3) * 4;
    const float* pnc = g_nc2 + ((l >> 3) * NO + wi0) * 2 + (l & 7) * 4;
    const float* pso = g_so2 + ((l >> 3) * NO + wi0) * 2 + (l & 7) * 4;
    const int orow4 = 4 * NO * 2;            // +4 j-pair rows (second granule)
    const int xstep = (J_CH / 2) * NB * 2;   // floats per chunk, x-side
    const int ostep = (J_CH / 2) * NO * 2;   // floats per chunk, o-side

    // hoisted destinations (phase 0; phase 1 = +WBUF_BYTES)
    const unsigned dcx  = sb + (unsigned)(l * 16);
    const unsigned dsx  = sb + (unsigned)(WB_SX * 4 + l * 16);
    const unsigned dnc0 = sb + (unsigned)(WB_NC * 4 + l * 16);
    const unsigned dnc1 = sb + (unsigned)(WB_NC * 4 + (l + 32) * 16);
    const unsigned dso0 = sb + (unsigned)(WB_SO * 4 + l * 16);
    const unsigned dso1 = sb + (unsigned)(WB_SO * 4 + (l + 32) * 16);

    #define ISSUE(pb)                                                   \
        do {                                                            \
            cp16(dcx + (pb), pxc);                                      \
            cp16(dsx + (pb), pxs);                                      \
            cp16(dnc0 + (pb), pnc); cp16(dnc1 + (pb), pnc + orow4);     \
            cp16(dso0 + (pb), pso); cp16(dso1 + (pb), pso + orow4);     \
            asm volatile("cp.async.commit_group;\n" ::);                \
            pxc += xstep; pxs += xstep; pnc += ostep; pso += ostep;     \
        } while (0)

    float a00 = 0.f, a01 = 0.f, a10 = 0.f, a11 = 0.f;

    ISSUE(0u);
    ISSUE((unsigned)WBUF_BYTES);

    #pragma unroll 1
    for (int c = 0; c < NCHUNK; ++c) {
        if (c < NCHUNK - 1) asm volatile("cp.async.wait_group 1;\n" ::);
        else                asm volatile("cp.async.wait_group 0;\n" ::);
        __syncwarp();

        const float* buf = wbuf + (c & 1) * WBUF_FLOATS;
        const float* cxb = buf +         tx * 4;   // row stride 16 floats
        const float* sxb = buf + WB_SX + tx * 4;
        const float* ncb = buf + WB_NC + ty * 4;   // row stride 32 floats
        const float* sob = buf + WB_SO + ty * 4;

        #pragma unroll
        for (int jp = 0; jp < J_CH / 2; jp += 2) {   // 4 j per iter, imm offsets
            const ulonglong2 cxA = *(const ulonglong2*)(cxb + (jp    ) * 16);
            const ulonglong2 cxB = *(const ulonglong2*)(cxb + (jp + 1) * 16);
            const ulonglong2 sxA = *(const ulonglong2*)(sxb + (jp    ) * 16);
            const ulonglong2 sxB = *(const ulonglong2*)(sxb + (jp + 1) * 16);
            const ulonglong2 nA  = *(const ulonglong2*)(ncb + (jp    ) * 32);
            const ulonglong2 nB  = *(const ulonglong2*)(ncb + (jp + 1) * 32);
            const ulonglong2 oA  = *(const ulonglong2*)(sob + (jp    ) * 32);
            const ulonglong2 oB  = *(const ulonglong2*)(sob + (jp + 1) * 32);

            // (b0, i0) / (b0, i1)
            QCELL(a00, cxA.x, sxA.x, cxB.x, sxB.x, nA.x, oA.x, nB.x, oB.x);
            QCELL(a01, cxA.x, sxA.x, cxB.x, sxB.x, nA.y, oA.y, nB.y, oB.y);
            // (b1, i0) / (b1, i1)
            QCELL(a10, cxA.y, sxA.y, cxB.y, sxB.y, nA.x, oA.x, nB.x, oB.x);
            QCELL(a11, cxA.y, sxA.y, cxB.y, sxB.y, nA.y, oA.y, nB.y, oB.y);
        }
        __syncwarp();   // all lanes' reads of this phase done before refill
        if (c + 2 < NCHUNK) ISSUE((c & 1) ? (unsigned)WBUF_BYTES : 0u);
    }
    #undef ISSUE

    const int b0 = wb0 + tx * 2;
    const int i0 = wi0 + ty * 2;
    float2 r0, r1;
    r0.x = fmaf(negK, a00, (float)NI);
    r0.y = fmaf(negK, a01, (float)NI);
    r1.x = fmaf(negK, a10, (float)NI);
    r1.y = fmaf(negK, a11, (float)NI);
    *(float2*)(out + (b0 + 0) * NO + i0) = r0;
    *(float2*)(out + (b0 + 1) * NO + i0) = r1;
}

extern "C" void kernel_launch(void* const* d_in, const int* in_sizes, int n_in,
                              void* d_out, int out_size) {
    const float* x   = (const float*)d_in[0];   // input_matrix [2048, 256]
    const float* off = (const float*)d_in[1];   // phase_offset [256, 256]
    float* out = (float*)d_out;                 // [2048, 256]

    // Physics constants
    const double PI     = 3.14159265358979323846;
    const double RADIUS = 5e-6;
    const double KAPPA  = 0.1;
    const double N_EFF  = 3.48;
    const double LAMBDA = 1.55e-6;
    const double LOSS_A = 0.99;

    const double t   = sqrt(1.0 - KAPPA);
    const double a   = LOSS_A;
    const double rho = a * t;
    const double phi0 = fmod(2.0 * PI * N_EFF * (2.0 * PI * RADIUS) / LAMBDA, 2.0 * PI);

    const float Qc      = (float)(1.0 + rho * rho);
    const float two_rho = (float)(2.0 * rho);
    const float negK    = (float)(-(1.0 - t * t) * (1.0 - a * a));

    unsigned int qbits;
    memcpy(&qbits, &Qc, 4);
    const ull Q2 = ((ull)qbits << 32) | qbits;   // packed (Qc, Qc)

    prep_all<<<576, 256>>>(x, off, (float)phi0, two_rho);

    cudaFuncSetAttribute(photonic_main,
                         cudaFuncAttributeMaxDynamicSharedMemorySize, SMEM_BYTES);
    dim3 grid(NB / 16, NO / 32);   // (128, 8) = 1024 CTAs
    photonic_main<<<grid, 128, SMEM_BYTES>>>(out, Q2, negK);
}